// round 11
// baseline (speedup 1.0000x reference)
#include <cuda_runtime.h>
#include <cstdint>

// LIF forward scan, 4 time steps. x/out: [4, N] fp32, N = 8,388,608.
// Forward value of the surrogate spike == hard threshold (mem > 0.5).
// HBM-bound streaming: 134 MiB read + 134 MiB write.
//
// R10: R9 config (flat grid, 1024-thread blocks, 30-reg body, .cs stores)
// with ONE change: loads use __ldcg (L2-only, no L1 allocation). L1 was
// 42% busy with a guaranteed-0% hit rate; .cg removes L1 tag/fill work
// from the load path. Everything else byte-identical to the best-known.

static constexpr int STEP    = 4;
static constexpr int THREADS = 1024;

__device__ __forceinline__ void lif_step(float4& mem, const float4 xin, float4& s) {
    mem.x = fmaf(mem.x, 0.25f, xin.x); mem.y = fmaf(mem.y, 0.25f, xin.y);
    mem.z = fmaf(mem.z, 0.25f, xin.z); mem.w = fmaf(mem.w, 0.25f, xin.w);
    s.x = mem.x > 0.5f ? 1.f : 0.f;  s.y = mem.y > 0.5f ? 1.f : 0.f;
    s.z = mem.z > 0.5f ? 1.f : 0.f;  s.w = mem.w > 0.5f ? 1.f : 0.f;
    mem.x = s.x > 0.f ? 0.f : mem.x; mem.y = s.y > 0.f ? 0.f : mem.y;
    mem.z = s.z > 0.f ? 0.f : mem.z; mem.w = s.w > 0.f ? 0.f : mem.w;
}

__global__ __launch_bounds__(THREADS)
void lif_fwd_kernel(const float4* __restrict__ x, float4* __restrict__ out, int n4) {
    int i = blockIdx.x * THREADS + threadIdx.x;
    if (i >= n4) return;

    // 4 independent front-batched LDG.128 (one per time step), L2-only (.cg).
    float4 x0 = __ldcg(&x[0 * (size_t)n4 + i]);
    float4 x1 = __ldcg(&x[1 * (size_t)n4 + i]);
    float4 x2 = __ldcg(&x[2 * (size_t)n4 + i]);
    float4 x3 = __ldcg(&x[3 * (size_t)n4 + i]);

    float4 mem = make_float4(0.f, 0.f, 0.f, 0.f);
    float4 s;

    lif_step(mem, x0, s);
    __stcs(&out[0 * (size_t)n4 + i], s);

    lif_step(mem, x1, s);
    __stcs(&out[1 * (size_t)n4 + i], s);

    lif_step(mem, x2, s);
    __stcs(&out[2 * (size_t)n4 + i], s);

    lif_step(mem, x3, s);
    __stcs(&out[3 * (size_t)n4 + i], s);
}

extern "C" void kernel_launch(void* const* d_in, const int* in_sizes, int n_in,
                              void* d_out, int out_size) {
    const float* x = (const float*)d_in[0];
    float* out = (float*)d_out;

    int total = in_sizes[0];          // STEP * N
    int n = total / STEP;             // 8,388,608 elements per step
    int n4 = n / 4;                   // 2,097,152 float4 per step

    int blocks = (n4 + THREADS - 1) / THREADS;  // 2048
    lif_fwd_kernel<<<blocks, THREADS>>>((const float4*)x, (float4*)out, n4);
}

// round 12
// speedup vs baseline: 1.0190x; 1.0190x over previous
#include <cuda_runtime.h>
#include <cstdint>

// LIF forward scan, 4 time steps. x/out: [4, N] fp32, N = 8,388,608.
// Forward value of the surrogate spike == hard threshold (mem > 0.5).
// HBM-bound streaming: 134 MiB read + 134 MiB write.
//
// FINAL (== R9, the measured best at 43.46us bench / 35.7us in-kernel /
// 75.5% DRAM ~ 7.4 TB/s effective, ~92% of spec):
//  - flat grid, 1024-thread blocks (2048 CTAs): fresh CTAs keep the
//    L1tex queue fed with front-batched loads (persistent grid-stride
//    variants de-batched loads behind stores + loop branch: -8%).
//  - 1 float4/thread, 30 regs, full 2048 thr/SM occupancy (coarsening
//    pushed regs to 40 and lost a CTA/SM: -13%).
//  - evict-first (.cs) on both loads and stores: zero reuse either
//    direction; evict-normal stores polluted L2 and regressed.
//  - .cg loads tested: neutral-to-worse (all LDG transit the L1tex
//    wavefront queue regardless of allocation policy).

static constexpr int STEP    = 4;
static constexpr int THREADS = 1024;

__device__ __forceinline__ void lif_step(float4& mem, const float4 xin, float4& s) {
    mem.x = fmaf(mem.x, 0.25f, xin.x); mem.y = fmaf(mem.y, 0.25f, xin.y);
    mem.z = fmaf(mem.z, 0.25f, xin.z); mem.w = fmaf(mem.w, 0.25f, xin.w);
    s.x = mem.x > 0.5f ? 1.f : 0.f;  s.y = mem.y > 0.5f ? 1.f : 0.f;
    s.z = mem.z > 0.5f ? 1.f : 0.f;  s.w = mem.w > 0.5f ? 1.f : 0.f;
    mem.x = s.x > 0.f ? 0.f : mem.x; mem.y = s.y > 0.f ? 0.f : mem.y;
    mem.z = s.z > 0.f ? 0.f : mem.z; mem.w = s.w > 0.f ? 0.f : mem.w;
}

__global__ __launch_bounds__(THREADS)
void lif_fwd_kernel(const float4* __restrict__ x, float4* __restrict__ out, int n4) {
    int i = blockIdx.x * THREADS + threadIdx.x;
    if (i >= n4) return;

    // 4 independent front-batched LDG.128 (one per time step), evict-first.
    float4 x0 = __ldcs(&x[0 * (size_t)n4 + i]);
    float4 x1 = __ldcs(&x[1 * (size_t)n4 + i]);
    float4 x2 = __ldcs(&x[2 * (size_t)n4 + i]);
    float4 x3 = __ldcs(&x[3 * (size_t)n4 + i]);

    float4 mem = make_float4(0.f, 0.f, 0.f, 0.f);
    float4 s;

    lif_step(mem, x0, s);
    __stcs(&out[0 * (size_t)n4 + i], s);

    lif_step(mem, x1, s);
    __stcs(&out[1 * (size_t)n4 + i], s);

    lif_step(mem, x2, s);
    __stcs(&out[2 * (size_t)n4 + i], s);

    lif_step(mem, x3, s);
    __stcs(&out[3 * (size_t)n4 + i], s);
}

extern "C" void kernel_launch(void* const* d_in, const int* in_sizes, int n_in,
                              void* d_out, int out_size) {
    const float* x = (const float*)d_in[0];
    float* out = (float*)d_out;

    int total = in_sizes[0];          // STEP * N
    int n = total / STEP;             // 8,388,608 elements per step
    int n4 = n / 4;                   // 2,097,152 float4 per step

    int blocks = (n4 + THREADS - 1) / THREADS;  // 2048
    lif_fwd_kernel<<<blocks, THREADS>>>((const float4*)x, (float4*)out, n4);
}